// round 6
// baseline (speedup 1.0000x reference)
#include <cuda_runtime.h>
#include <cstdint>
#include <cstddef>

#define Bb 8
#define Ss 4096
#define Dd 64
#define ROWS 32
#define KT 64

__device__ float g_rowsum[Bb * Ss];
__device__ int   g_mask_kind;   // 0 = int32, 1 = bytes(bool), 2 = float32

// Classify the mask buffer dtype by scanning its first 64K 32-bit words.
__global__ void detect_mask(const unsigned* __restrict__ M) {
    __shared__ int s_bytes, s_float;
    if (threadIdx.x == 0) { s_bytes = 0; s_float = 0; }
    __syncthreads();
    int anyBig = 0, anyFloat = 0;
    for (int i = threadIdx.x; i < 65536; i += 256) {
        unsigned w = M[i];
        anyBig   |= (w > 1u);
        anyFloat |= (w == 0x3F800000u);
    }
    if (anyBig)   atomicOr(&s_bytes, 1);
    if (anyFloat) atomicOr(&s_float, 1);
    __syncthreads();
    if (threadIdx.x == 0)
        g_mask_kind = s_float ? 2 : (s_bytes ? 1 : 0);
}

// Packed 2-wide fp32 FMA (SASS FFMA2) — only reachable via PTX fma.rn.f32x2.
__device__ __forceinline__ float2 ffma2(float2 a, float2 b, float2 c) {
    float2 d;
    asm("fma.rn.f32x2 %0, %1, %2, %3;"
        : "=l"(reinterpret_cast<unsigned long long&>(d))
        : "l"(reinterpret_cast<unsigned long long&>(a)),
          "l"(reinterpret_cast<unsigned long long&>(b)),
          "l"(reinterpret_cast<unsigned long long&>(c)));
    return d;
}

__device__ __forceinline__ float2 dup2(float f) {
    float2 d;
    asm("mov.b64 %0, {%1, %1};"
        : "=l"(reinterpret_cast<unsigned long long&>(d)) : "f"(f));
    return d;
}

// Fast exp via all-FFMA path (avoid MUFU EX2 throughput wall: rt=8/SMSP).
__device__ __forceinline__ float fexp(float x) {
    x = fminf(fmaxf(x, -80.0f), 80.0f);
    float t = x * 1.4426950408889634f;
    float r = t + 12582912.0f;              // 1.5*2^23: round-to-nearest in mantissa
    int   ni = __float_as_int(r) - 0x4B400000;
    float n = r - 12582912.0f;
    float f = t - n;                        // f in [-0.5, 0.5]
    float w = f * 0.6931471805599453f;      // |w| <= 0.3466
    float p = fmaf(w, 0.008333333333f, 0.041666666667f);
    p = fmaf(w, p, 0.166666666667f);
    p = fmaf(w, p, 0.5f);
    p = fmaf(w, p, 1.0f);
    p = fmaf(w, p, 1.0f);
    return __int_as_float(__float_as_int(p) + (ni << 23));
}

template<int KIND>
__device__ __forceinline__ bool mask_at(const void* __restrict__ M, size_t off) {
    if (KIND == 0) return ((const int*)M)[off] != 0;
    if (KIND == 1) return ((const uint8_t*)M)[off] != 0;
    return ((const float*)M)[off] != 0.0f;
}

template<int KIND>
__global__ __launch_bounds__(256, 2)
void attn_k1(const float* __restrict__ Qg, const float* __restrict__ Kg,
             const float* __restrict__ Vg, const void* __restrict__ Mg,
             float* __restrict__ ctxg, float* __restrict__ attng) {
    if (g_mask_kind != KIND) return;   // uniform early exit for wrong-dtype variant

    // Static smem: 8192 (Q) + 16384 (K) + 16384 (V) + 8192 (E) = 48 KB
    __shared__ float4 Qs[ROWS * 16];      // [row][d4]
    __shared__ float4 Ks[16 * 64];        // [d4][k]
    __shared__ float4 Vs[64 * 16];        // [k][d4]
    __shared__ float  Es[64 * 32];        // [k][row ^ (k&31)]  (XOR swizzle)

    const int t  = threadIdx.x;
    const int cg = t & 15;                // column group: cols = cg + 16j
    const int rp = t >> 4;                // 0..15: rows rp and rp+16
    const int b  = blockIdx.x >> 7;       // 128 q-tiles per batch
    const int q0 = (blockIdx.x & 127) * ROWS;
    const size_t row0g = (size_t)b * Ss + q0;

    {
        const float4* Qgm = (const float4*)(Qg + row0g * Dd);
        Qs[t]       = Qgm[t];
        Qs[t + 256] = Qgm[t + 256];
    }

    // Packed context accumulators: rows A/B x component pairs (x,y),(z,w)
    float2 accA01 = make_float2(0.f, 0.f), accA23 = make_float2(0.f, 0.f);
    float2 accB01 = make_float2(0.f, 0.f), accB23 = make_float2(0.f, 0.f);
    float rs0 = 0.f, rs1 = 0.f;

    const size_t rowA = row0g + rp;
    const size_t rowB = row0g + rp + 16;

    __syncthreads();

    for (int kt = 0; kt < Ss / KT; kt++) {
        const int k0 = kt * KT;
        {
            const float4* Kgm = (const float4*)(Kg + ((size_t)b * Ss + k0) * Dd);
            const float4* Vgm = (const float4*)(Vg + ((size_t)b * Ss + k0) * Dd);
            #pragma unroll
            for (int m = 0; m < 4; m++) {
                int idx = t + 256 * m;
                int k = idx >> 4, d4 = idx & 15;
                Ks[d4 * 64 + k] = Kgm[idx];
                Vs[idx]         = Vgm[idx];
            }
        }
        __syncthreads();

        // --- QK^T packed: lo half accumulates even-d, hi half odd-d ---
        float2 p00 = make_float2(0.f,0.f), p01 = p00, p02 = p00, p03 = p00;
        float2 p10 = p00, p11 = p00, p12 = p00, p13 = p00;
        #pragma unroll
        for (int d4 = 0; d4 < 16; d4++) {
            float4 qa = Qs[rp * 16 + d4];
            float4 qb = Qs[(rp + 16) * 16 + d4];
            float4 k0v = Ks[d4 * 64 + cg];
            float4 k1v = Ks[d4 * 64 + cg + 16];
            float4 k2v = Ks[d4 * 64 + cg + 32];
            float4 k3v = Ks[d4 * 64 + cg + 48];
            float2 qa01 = make_float2(qa.x, qa.y), qa23 = make_float2(qa.z, qa.w);
            float2 qb01 = make_float2(qb.x, qb.y), qb23 = make_float2(qb.z, qb.w);
            p00 = ffma2(qa01, make_float2(k0v.x,k0v.y), p00);
            p00 = ffma2(qa23, make_float2(k0v.z,k0v.w), p00);
            p01 = ffma2(qa01, make_float2(k1v.x,k1v.y), p01);
            p01 = ffma2(qa23, make_float2(k1v.z,k1v.w), p01);
            p02 = ffma2(qa01, make_float2(k2v.x,k2v.y), p02);
            p02 = ffma2(qa23, make_float2(k2v.z,k2v.w), p02);
            p03 = ffma2(qa01, make_float2(k3v.x,k3v.y), p03);
            p03 = ffma2(qa23, make_float2(k3v.z,k3v.w), p03);
            p10 = ffma2(qb01, make_float2(k0v.x,k0v.y), p10);
            p10 = ffma2(qb23, make_float2(k0v.z,k0v.w), p10);
            p11 = ffma2(qb01, make_float2(k1v.x,k1v.y), p11);
            p11 = ffma2(qb23, make_float2(k1v.z,k1v.w), p11);
            p12 = ffma2(qb01, make_float2(k2v.x,k2v.y), p12);
            p12 = ffma2(qb23, make_float2(k2v.z,k2v.w), p12);
            p13 = ffma2(qb01, make_float2(k3v.x,k3v.y), p13);
            p13 = ffma2(qb23, make_float2(k3v.z,k3v.w), p13);
        }

        // --- mask + exp + store unnormalized e ---
        float sv0[4] = {p00.x + p00.y, p01.x + p01.y, p02.x + p02.y, p03.x + p03.y};
        float sv1[4] = {p10.x + p10.y, p11.x + p11.y, p12.x + p12.y, p13.x + p13.y};
        #pragma unroll
        for (int j = 0; j < 4; j++) {
            int kc = cg + 16 * j;
            size_t colg = (size_t)k0 + kc;
            bool mA = mask_at<KIND>(Mg, rowA * Ss + colg);
            bool mB = mask_at<KIND>(Mg, rowB * Ss + colg);
            float eA = mA ? 0.f : fexp(sv0[j] * 0.125f);
            float eB = mB ? 0.f : fexp(sv1[j] * 0.125f);
            attng[rowA * Ss + colg] = eA;
            attng[rowB * Ss + colg] = eB;
            Es[kc * 32 + (rp ^ (kc & 31))]        = eA;
            Es[kc * 32 + ((rp + 16) ^ (kc & 31))] = eB;
            rs0 += eA;
            rs1 += eB;
        }
        __syncthreads();

        // --- context accumulate (packed): acc[r][4cg..4cg+3] += e[r][k]*V[k][:] ---
        #pragma unroll 8
        for (int k = 0; k < KT; k++) {
            float4 vv = Vs[k * 16 + cg];
            float eA = Es[k * 32 + (rp ^ (k & 31))];
            float eB = Es[k * 32 + ((rp + 16) ^ (k & 31))];
            float2 eA2 = dup2(eA);
            float2 eB2 = dup2(eB);
            float2 v01 = make_float2(vv.x, vv.y), v23 = make_float2(vv.z, vv.w);
            accA01 = ffma2(eA2, v01, accA01);
            accA23 = ffma2(eA2, v23, accA23);
            accB01 = ffma2(eB2, v01, accB01);
            accB23 = ffma2(eB2, v23, accB23);
        }
        __syncthreads();
    }

    // Row-sum reduce across the 16 cg lanes (xor offsets <=8 stay in 16-lane half)
    #pragma unroll
    for (int o = 8; o; o >>= 1) {
        rs0 += __shfl_xor_sync(0xffffffffu, rs0, o);
        rs1 += __shfl_xor_sync(0xffffffffu, rs1, o);
    }
    float inv0 = __fdividef(1.0f, rs0);
    float inv1 = __fdividef(1.0f, rs1);

    float4 acc0 = make_float4(accA01.x * inv0, accA01.y * inv0,
                              accA23.x * inv0, accA23.y * inv0);
    float4 acc1 = make_float4(accB01.x * inv1, accB01.y * inv1,
                              accB23.x * inv1, accB23.y * inv1);

    float4* Cg = (float4*)ctxg;
    Cg[rowA * 16 + cg] = acc0;
    Cg[rowB * 16 + cg] = acc1;

    if (cg == 0) {
        g_rowsum[rowA] = rs0;
        g_rowsum[rowB] = rs1;
    }
}

// Normalize attn rows by 1/rowsum. 32768 blocks x 256 thr, 4 float4 each.
__global__ __launch_bounds__(256)
void attn_k2(float* __restrict__ attng) {
    const int row = blockIdx.x;
    const float inv = __fdividef(1.0f, g_rowsum[row]);
    float4* a = (float4*)(attng + (size_t)row * Ss);
    #pragma unroll
    for (int i = 0; i < 4; i++) {
        int idx = threadIdx.x + 256 * i;
        float4 v = a[idx];
        v.x *= inv; v.y *= inv; v.z *= inv; v.w *= inv;
        a[idx] = v;
    }
}

extern "C" void kernel_launch(void* const* d_in, const int* in_sizes, int n_in,
                              void* d_out, int out_size) {
    const float* Q = (const float*)d_in[0];
    const float* K = (const float*)d_in[1];
    const float* V = (const float*)d_in[2];
    const void*  M = d_in[3];

    float* ctx  = (float*)d_out;                       // [B,S,D]
    float* attn = ctx + (size_t)Bb * Ss * Dd;          // [B,S,S]

    detect_mask<<<1, 256>>>((const unsigned*)M);
    attn_k1<0><<<Bb * (Ss / ROWS), 256>>>(Q, K, V, M, ctx, attn);
    attn_k1<1><<<Bb * (Ss / ROWS), 256>>>(Q, K, V, M, ctx, attn);
    attn_k1<2><<<Bb * (Ss / ROWS), 256>>>(Q, K, V, M, ctx, attn);
    attn_k2<<<Bb * Ss, 256>>>(attn);
}

// round 7
// speedup vs baseline: 1.0022x; 1.0022x over previous
#include <cuda_runtime.h>
#include <cstdint>
#include <cstddef>

#define Bb 8
#define Ss 4096
#define Dd 64
#define ROWS 32
#define KT 64

__device__ float g_rowsum[Bb * Ss];
__device__ int   g_mask_kind;   // 0 = int32, 1 = bytes(bool), 2 = float32

// Classify the mask buffer dtype by scanning its first 64K 32-bit words.
__global__ void detect_mask(const unsigned* __restrict__ M) {
    __shared__ int s_bytes, s_float;
    if (threadIdx.x == 0) { s_bytes = 0; s_float = 0; }
    __syncthreads();
    int anyBig = 0, anyFloat = 0;
    for (int i = threadIdx.x; i < 65536; i += 256) {
        unsigned w = M[i];
        anyBig   |= (w > 1u);
        anyFloat |= (w == 0x3F800000u);
    }
    if (anyBig)   atomicOr(&s_bytes, 1);
    if (anyFloat) atomicOr(&s_float, 1);
    __syncthreads();
    if (threadIdx.x == 0)
        g_mask_kind = s_float ? 2 : (s_bytes ? 1 : 0);
}

// Packed 2-wide fp32 FMA (SASS FFMA2) — only reachable via PTX fma.rn.f32x2.
__device__ __forceinline__ float2 ffma2(float2 a, float2 b, float2 c) {
    float2 d;
    asm("fma.rn.f32x2 %0, %1, %2, %3;"
        : "=l"(reinterpret_cast<unsigned long long&>(d))
        : "l"(reinterpret_cast<unsigned long long&>(a)),
          "l"(reinterpret_cast<unsigned long long&>(b)),
          "l"(reinterpret_cast<unsigned long long&>(c)));
    return d;
}

__device__ __forceinline__ float2 dup2(float f) {
    float2 d;
    asm("mov.b64 %0, {%1, %1};"
        : "=l"(reinterpret_cast<unsigned long long&>(d)) : "f"(f));
    return d;
}

// Fast exp via all-FFMA path (avoid MUFU EX2 throughput wall: rt=8/SMSP).
__device__ __forceinline__ float fexp(float x) {
    x = fminf(fmaxf(x, -80.0f), 80.0f);
    float t = x * 1.4426950408889634f;
    float r = t + 12582912.0f;              // 1.5*2^23: round-to-nearest in mantissa
    int   ni = __float_as_int(r) - 0x4B400000;
    float n = r - 12582912.0f;
    float f = t - n;                        // f in [-0.5, 0.5]
    float w = f * 0.6931471805599453f;      // |w| <= 0.3466
    float p = fmaf(w, 0.008333333333f, 0.041666666667f);
    p = fmaf(w, p, 0.166666666667f);
    p = fmaf(w, p, 0.5f);
    p = fmaf(w, p, 1.0f);
    p = fmaf(w, p, 1.0f);
    return __int_as_float(__float_as_int(p) + (ni << 23));
}

template<int KIND>
__device__ __forceinline__ bool mask_at(const void* __restrict__ M, size_t off) {
    if (KIND == 0) return ((const int*)M)[off] != 0;
    if (KIND == 1) return ((const uint8_t*)M)[off] != 0;
    return ((const float*)M)[off] != 0.0f;
}

template<int KIND>
__global__ __launch_bounds__(256, 2)
void attn_k1(const float* __restrict__ Qg, const float* __restrict__ Kg,
             const float* __restrict__ Vg, const void* __restrict__ Mg,
             float* __restrict__ ctxg, float* __restrict__ attng) {
    if (g_mask_kind != KIND) return;   // uniform early exit for wrong-dtype variant

    // Static smem: 8192 (Q) + 16384 (K) + 16384 (V) + 8192 (E) = 48 KB
    __shared__ float4 Qs[ROWS * 16];      // [row][d4]
    __shared__ float4 Ks[16 * 64];        // [d4][k]
    __shared__ float4 Vs[64 * 16];        // [k][d4]
    __shared__ float  Es[64 * 32];        // [k][row ^ (k&31)]  (XOR swizzle)

    const int t  = threadIdx.x;
    const int cg = t & 15;                // column group: cols = cg + 16j
    const int rp = t >> 4;                // 0..15: rows rp and rp+16
    const int b  = blockIdx.x >> 7;       // 128 q-tiles per batch
    const int q0 = (blockIdx.x & 127) * ROWS;
    const size_t row0g = (size_t)b * Ss + q0;

    {
        const float4* Qgm = (const float4*)(Qg + row0g * Dd);
        Qs[t]       = Qgm[t];
        Qs[t + 256] = Qgm[t + 256];
    }

    // Packed context accumulators: rows A/B x component pairs (x,y),(z,w)
    float2 accA01 = make_float2(0.f, 0.f), accA23 = make_float2(0.f, 0.f);
    float2 accB01 = make_float2(0.f, 0.f), accB23 = make_float2(0.f, 0.f);
    float rs0 = 0.f, rs1 = 0.f;

    const size_t rowA = row0g + rp;
    const size_t rowB = row0g + rp + 16;

    __syncthreads();

    for (int kt = 0; kt < Ss / KT; kt++) {
        const int k0 = kt * KT;
        {
            const float4* Kgm = (const float4*)(Kg + ((size_t)b * Ss + k0) * Dd);
            const float4* Vgm = (const float4*)(Vg + ((size_t)b * Ss + k0) * Dd);
            #pragma unroll
            for (int m = 0; m < 4; m++) {
                int idx = t + 256 * m;
                int k = idx >> 4, d4 = idx & 15;
                Ks[d4 * 64 + k] = Kgm[idx];
                Vs[idx]         = Vgm[idx];
            }
        }
        __syncthreads();

        // --- QK^T packed: lo half accumulates even-d, hi half odd-d ---
        float2 p00 = make_float2(0.f,0.f), p01 = p00, p02 = p00, p03 = p00;
        float2 p10 = p00, p11 = p00, p12 = p00, p13 = p00;
        #pragma unroll
        for (int d4 = 0; d4 < 16; d4++) {
            float4 qa = Qs[rp * 16 + d4];
            float4 qb = Qs[(rp + 16) * 16 + d4];
            float4 k0v = Ks[d4 * 64 + cg];
            float4 k1v = Ks[d4 * 64 + cg + 16];
            float4 k2v = Ks[d4 * 64 + cg + 32];
            float4 k3v = Ks[d4 * 64 + cg + 48];
            float2 qa01 = make_float2(qa.x, qa.y), qa23 = make_float2(qa.z, qa.w);
            float2 qb01 = make_float2(qb.x, qb.y), qb23 = make_float2(qb.z, qb.w);
            p00 = ffma2(qa01, make_float2(k0v.x,k0v.y), p00);
            p00 = ffma2(qa23, make_float2(k0v.z,k0v.w), p00);
            p01 = ffma2(qa01, make_float2(k1v.x,k1v.y), p01);
            p01 = ffma2(qa23, make_float2(k1v.z,k1v.w), p01);
            p02 = ffma2(qa01, make_float2(k2v.x,k2v.y), p02);
            p02 = ffma2(qa23, make_float2(k2v.z,k2v.w), p02);
            p03 = ffma2(qa01, make_float2(k3v.x,k3v.y), p03);
            p03 = ffma2(qa23, make_float2(k3v.z,k3v.w), p03);
            p10 = ffma2(qb01, make_float2(k0v.x,k0v.y), p10);
            p10 = ffma2(qb23, make_float2(k0v.z,k0v.w), p10);
            p11 = ffma2(qb01, make_float2(k1v.x,k1v.y), p11);
            p11 = ffma2(qb23, make_float2(k1v.z,k1v.w), p11);
            p12 = ffma2(qb01, make_float2(k2v.x,k2v.y), p12);
            p12 = ffma2(qb23, make_float2(k2v.z,k2v.w), p12);
            p13 = ffma2(qb01, make_float2(k3v.x,k3v.y), p13);
            p13 = ffma2(qb23, make_float2(k3v.z,k3v.w), p13);
        }

        // --- mask + exp + store unnormalized e ---
        float sv0[4] = {p00.x + p00.y, p01.x + p01.y, p02.x + p02.y, p03.x + p03.y};
        float sv1[4] = {p10.x + p10.y, p11.x + p11.y, p12.x + p12.y, p13.x + p13.y};
        #pragma unroll
        for (int j = 0; j < 4; j++) {
            int kc = cg + 16 * j;
            size_t colg = (size_t)k0 + kc;
            bool mA = mask_at<KIND>(Mg, rowA * Ss + colg);
            bool mB = mask_at<KIND>(Mg, rowB * Ss + colg);
            float eA = mA ? 0.f : fexp(sv0[j] * 0.125f);
            float eB = mB ? 0.f : fexp(sv1[j] * 0.125f);
            attng[rowA * Ss + colg] = eA;
            attng[rowB * Ss + colg] = eB;
            Es[kc * 32 + (rp ^ (kc & 31))]        = eA;
            Es[kc * 32 + ((rp + 16) ^ (kc & 31))] = eB;
            rs0 += eA;
            rs1 += eB;
        }
        __syncthreads();

        // --- context accumulate (packed): acc[r][4cg..4cg+3] += e[r][k]*V[k][:] ---
        #pragma unroll 8
        for (int k = 0; k < KT; k++) {
            float4 vv = Vs[k * 16 + cg];
            float eA = Es[k * 32 + (rp ^ (k & 31))];
            float eB = Es[k * 32 + ((rp + 16) ^ (k & 31))];
            float2 eA2 = dup2(eA);
            float2 eB2 = dup2(eB);
            float2 v01 = make_float2(vv.x, vv.y), v23 = make_float2(vv.z, vv.w);
            accA01 = ffma2(eA2, v01, accA01);
            accA23 = ffma2(eA2, v23, accA23);
            accB01 = ffma2(eB2, v01, accB01);
            accB23 = ffma2(eB2, v23, accB23);
        }
        __syncthreads();
    }

    // Row-sum reduce across the 16 cg lanes (xor offsets <=8 stay in 16-lane half)
    #pragma unroll
    for (int o = 8; o; o >>= 1) {
        rs0 += __shfl_xor_sync(0xffffffffu, rs0, o);
        rs1 += __shfl_xor_sync(0xffffffffu, rs1, o);
    }
    float inv0 = __fdividef(1.0f, rs0);
    float inv1 = __fdividef(1.0f, rs1);

    float4 acc0 = make_float4(accA01.x * inv0, accA01.y * inv0,
                              accA23.x * inv0, accA23.y * inv0);
    float4 acc1 = make_float4(accB01.x * inv1, accB01.y * inv1,
                              accB23.x * inv1, accB23.y * inv1);

    float4* Cg = (float4*)ctxg;
    Cg[rowA * 16 + cg] = acc0;
    Cg[rowB * 16 + cg] = acc1;

    if (cg == 0) {
        g_rowsum[rowA] = rs0;
        g_rowsum[rowB] = rs1;
    }
}

// Normalize attn rows by 1/rowsum. 32768 blocks x 256 thr, 4 float4 each.
__global__ __launch_bounds__(256)
void attn_k2(float* __restrict__ attng) {
    const int row = blockIdx.x;
    const float inv = __fdividef(1.0f, g_rowsum[row]);
    float4* a = (float4*)(attng + (size_t)row * Ss);
    #pragma unroll
    for (int i = 0; i < 4; i++) {
        int idx = threadIdx.x + 256 * i;
        float4 v = a[idx];
        v.x *= inv; v.y *= inv; v.z *= inv; v.w *= inv;
        a[idx] = v;
    }
}

extern "C" void kernel_launch(void* const* d_in, const int* in_sizes, int n_in,
                              void* d_out, int out_size) {
    const float* Q = (const float*)d_in[0];
    const float* K = (const float*)d_in[1];
    const float* V = (const float*)d_in[2];
    const void*  M = d_in[3];

    float* ctx  = (float*)d_out;                       // [B,S,D]
    float* attn = ctx + (size_t)Bb * Ss * Dd;          // [B,S,S]

    detect_mask<<<1, 256>>>((const unsigned*)M);
    attn_k1<0><<<Bb * (Ss / ROWS), 256>>>(Q, K, V, M, ctx, attn);
    attn_k1<1><<<Bb * (Ss / ROWS), 256>>>(Q, K, V, M, ctx, attn);
    attn_k1<2><<<Bb * (Ss / ROWS), 256>>>(Q, K, V, M, ctx, attn);
    attn_k2<<<Bb * Ss, 256>>>(attn);
}

// round 8
// speedup vs baseline: 1.0024x; 1.0002x over previous
#include <cuda_runtime.h>
#include <cstdint>
#include <cstddef>

#define Bb 8
#define Ss 4096
#define Dd 64
#define ROWS 32
#define KT 64

__device__ float g_rowsum[Bb * Ss];
__device__ int   g_mask_kind;   // 0 = int32, 1 = bytes(bool), 2 = float32

// Classify the mask buffer dtype by scanning its first 64K 32-bit words.
__global__ void detect_mask(const unsigned* __restrict__ M) {
    __shared__ int s_bytes, s_float;
    if (threadIdx.x == 0) { s_bytes = 0; s_float = 0; }
    __syncthreads();
    int anyBig = 0, anyFloat = 0;
    for (int i = threadIdx.x; i < 65536; i += 256) {
        unsigned w = M[i];
        anyBig   |= (w > 1u);
        anyFloat |= (w == 0x3F800000u);
    }
    if (anyBig)   atomicOr(&s_bytes, 1);
    if (anyFloat) atomicOr(&s_float, 1);
    __syncthreads();
    if (threadIdx.x == 0)
        g_mask_kind = s_float ? 2 : (s_bytes ? 1 : 0);
}

// Packed 2-wide fp32 FMA (SASS FFMA2) — only reachable via PTX fma.rn.f32x2.
__device__ __forceinline__ float2 ffma2(float2 a, float2 b, float2 c) {
    float2 d;
    asm("fma.rn.f32x2 %0, %1, %2, %3;"
        : "=l"(reinterpret_cast<unsigned long long&>(d))
        : "l"(reinterpret_cast<unsigned long long&>(a)),
          "l"(reinterpret_cast<unsigned long long&>(b)),
          "l"(reinterpret_cast<unsigned long long&>(c)));
    return d;
}

__device__ __forceinline__ float2 dup2(float f) {
    float2 d;
    asm("mov.b64 %0, {%1, %1};"
        : "=l"(reinterpret_cast<unsigned long long&>(d)) : "f"(f));
    return d;
}

// Fast exp via all-FFMA path (avoid MUFU EX2 throughput wall: rt=8/SMSP).
__device__ __forceinline__ float fexp(float x) {
    x = fminf(fmaxf(x, -80.0f), 80.0f);
    float t = x * 1.4426950408889634f;
    float r = t + 12582912.0f;              // 1.5*2^23: round-to-nearest in mantissa
    int   ni = __float_as_int(r) - 0x4B400000;
    float n = r - 12582912.0f;
    float f = t - n;                        // f in [-0.5, 0.5]
    float w = f * 0.6931471805599453f;      // |w| <= 0.3466
    float p = fmaf(w, 0.008333333333f, 0.041666666667f);
    p = fmaf(w, p, 0.166666666667f);
    p = fmaf(w, p, 0.5f);
    p = fmaf(w, p, 1.0f);
    p = fmaf(w, p, 1.0f);
    return __int_as_float(__float_as_int(p) + (ni << 23));
}

template<int KIND>
__device__ __forceinline__ bool mask_at(const void* __restrict__ M, size_t off) {
    if (KIND == 0) return ((const int*)M)[off] != 0;
    if (KIND == 1) return ((const uint8_t*)M)[off] != 0;
    return ((const float*)M)[off] != 0.0f;
}

template<int KIND>
__global__ __launch_bounds__(256, 2)
void attn_k1(const float* __restrict__ Qg, const float* __restrict__ Kg,
             const float* __restrict__ Vg, const void* __restrict__ Mg,
             float* __restrict__ ctxg, float* __restrict__ attng) {
    if (g_mask_kind != KIND) return;   // uniform early exit for wrong-dtype variant

    // Static smem: 8192 (Q) + 16384 (K) + 16384 (V) + 8192 (E) = 48 KB
    __shared__ float4 Qs[ROWS * 16];      // [row][d4]
    __shared__ float4 Ks[16 * 64];        // [d4][k]
    __shared__ float4 Vs[64 * 16];        // [k][d4]
    __shared__ float  Es[64 * 32];        // [k][row ^ (k&31)]  (XOR swizzle)

    const int t  = threadIdx.x;
    const int cg = t & 15;                // column group: cols = cg + 16j
    const int rp = t >> 4;                // 0..15: rows rp and rp+16
    const int b  = blockIdx.x >> 7;       // 128 q-tiles per batch
    const int q0 = (blockIdx.x & 127) * ROWS;
    const size_t row0g = (size_t)b * Ss + q0;

    {
        const float4* Qgm = (const float4*)(Qg + row0g * Dd);
        Qs[t]       = Qgm[t];
        Qs[t + 256] = Qgm[t + 256];
    }

    // Packed context accumulators: rows A/B x component pairs (x,y),(z,w)
    float2 accA01 = make_float2(0.f, 0.f), accA23 = make_float2(0.f, 0.f);
    float2 accB01 = make_float2(0.f, 0.f), accB23 = make_float2(0.f, 0.f);
    float rs0 = 0.f, rs1 = 0.f;

    const size_t rowA = row0g + rp;
    const size_t rowB = row0g + rp + 16;

    __syncthreads();

    for (int kt = 0; kt < Ss / KT; kt++) {
        const int k0 = kt * KT;
        {
            const float4* Kgm = (const float4*)(Kg + ((size_t)b * Ss + k0) * Dd);
            const float4* Vgm = (const float4*)(Vg + ((size_t)b * Ss + k0) * Dd);
            #pragma unroll
            for (int m = 0; m < 4; m++) {
                int idx = t + 256 * m;
                int k = idx >> 4, d4 = idx & 15;
                Ks[d4 * 64 + k] = Kgm[idx];
                Vs[idx]         = Vgm[idx];
            }
        }
        __syncthreads();

        // --- QK^T packed: lo half accumulates even-d, hi half odd-d ---
        float2 p00 = make_float2(0.f,0.f), p01 = p00, p02 = p00, p03 = p00;
        float2 p10 = p00, p11 = p00, p12 = p00, p13 = p00;
        #pragma unroll
        for (int d4 = 0; d4 < 16; d4++) {
            float4 qa = Qs[rp * 16 + d4];
            float4 qb = Qs[(rp + 16) * 16 + d4];
            float4 k0v = Ks[d4 * 64 + cg];
            float4 k1v = Ks[d4 * 64 + cg + 16];
            float4 k2v = Ks[d4 * 64 + cg + 32];
            float4 k3v = Ks[d4 * 64 + cg + 48];
            float2 qa01 = make_float2(qa.x, qa.y), qa23 = make_float2(qa.z, qa.w);
            float2 qb01 = make_float2(qb.x, qb.y), qb23 = make_float2(qb.z, qb.w);
            p00 = ffma2(qa01, make_float2(k0v.x,k0v.y), p00);
            p00 = ffma2(qa23, make_float2(k0v.z,k0v.w), p00);
            p01 = ffma2(qa01, make_float2(k1v.x,k1v.y), p01);
            p01 = ffma2(qa23, make_float2(k1v.z,k1v.w), p01);
            p02 = ffma2(qa01, make_float2(k2v.x,k2v.y), p02);
            p02 = ffma2(qa23, make_float2(k2v.z,k2v.w), p02);
            p03 = ffma2(qa01, make_float2(k3v.x,k3v.y), p03);
            p03 = ffma2(qa23, make_float2(k3v.z,k3v.w), p03);
            p10 = ffma2(qb01, make_float2(k0v.x,k0v.y), p10);
            p10 = ffma2(qb23, make_float2(k0v.z,k0v.w), p10);
            p11 = ffma2(qb01, make_float2(k1v.x,k1v.y), p11);
            p11 = ffma2(qb23, make_float2(k1v.z,k1v.w), p11);
            p12 = ffma2(qb01, make_float2(k2v.x,k2v.y), p12);
            p12 = ffma2(qb23, make_float2(k2v.z,k2v.w), p12);
            p13 = ffma2(qb01, make_float2(k3v.x,k3v.y), p13);
            p13 = ffma2(qb23, make_float2(k3v.z,k3v.w), p13);
        }

        // --- mask + exp + store unnormalized e ---
        float sv0[4] = {p00.x + p00.y, p01.x + p01.y, p02.x + p02.y, p03.x + p03.y};
        float sv1[4] = {p10.x + p10.y, p11.x + p11.y, p12.x + p12.y, p13.x + p13.y};
        #pragma unroll
        for (int j = 0; j < 4; j++) {
            int kc = cg + 16 * j;
            size_t colg = (size_t)k0 + kc;
            bool mA = mask_at<KIND>(Mg, rowA * Ss + colg);
            bool mB = mask_at<KIND>(Mg, rowB * Ss + colg);
            float eA = mA ? 0.f : fexp(sv0[j] * 0.125f);
            float eB = mB ? 0.f : fexp(sv1[j] * 0.125f);
            attng[rowA * Ss + colg] = eA;
            attng[rowB * Ss + colg] = eB;
            Es[kc * 32 + (rp ^ (kc & 31))]        = eA;
            Es[kc * 32 + ((rp + 16) ^ (kc & 31))] = eB;
            rs0 += eA;
            rs1 += eB;
        }
        __syncthreads();

        // --- context accumulate (packed): acc[r][4cg..4cg+3] += e[r][k]*V[k][:] ---
        #pragma unroll 8
        for (int k = 0; k < KT; k++) {
            float4 vv = Vs[k * 16 + cg];
            float eA = Es[k * 32 + (rp ^ (k & 31))];
            float eB = Es[k * 32 + ((rp + 16) ^ (k & 31))];
            float2 eA2 = dup2(eA);
            float2 eB2 = dup2(eB);
            float2 v01 = make_float2(vv.x, vv.y), v23 = make_float2(vv.z, vv.w);
            accA01 = ffma2(eA2, v01, accA01);
            accA23 = ffma2(eA2, v23, accA23);
            accB01 = ffma2(eB2, v01, accB01);
            accB23 = ffma2(eB2, v23, accB23);
        }
        __syncthreads();
    }

    // Row-sum reduce across the 16 cg lanes (xor offsets <=8 stay in 16-lane half)
    #pragma unroll
    for (int o = 8; o; o >>= 1) {
        rs0 += __shfl_xor_sync(0xffffffffu, rs0, o);
        rs1 += __shfl_xor_sync(0xffffffffu, rs1, o);
    }
    float inv0 = __fdividef(1.0f, rs0);
    float inv1 = __fdividef(1.0f, rs1);

    float4 acc0 = make_float4(accA01.x * inv0, accA01.y * inv0,
                              accA23.x * inv0, accA23.y * inv0);
    float4 acc1 = make_float4(accB01.x * inv1, accB01.y * inv1,
                              accB23.x * inv1, accB23.y * inv1);

    float4* Cg = (float4*)ctxg;
    Cg[rowA * 16 + cg] = acc0;
    Cg[rowB * 16 + cg] = acc1;

    if (cg == 0) {
        g_rowsum[rowA] = rs0;
        g_rowsum[rowB] = rs1;
    }
}

// Normalize attn rows by 1/rowsum. 32768 blocks x 256 thr, 4 float4 each.
__global__ __launch_bounds__(256)
void attn_k2(float* __restrict__ attng) {
    const int row = blockIdx.x;
    const float inv = __fdividef(1.0f, g_rowsum[row]);
    float4* a = (float4*)(attng + (size_t)row * Ss);
    #pragma unroll
    for (int i = 0; i < 4; i++) {
        int idx = threadIdx.x + 256 * i;
        float4 v = a[idx];
        v.x *= inv; v.y *= inv; v.z *= inv; v.w *= inv;
        a[idx] = v;
    }
}

extern "C" void kernel_launch(void* const* d_in, const int* in_sizes, int n_in,
                              void* d_out, int out_size) {
    const float* Q = (const float*)d_in[0];
    const float* K = (const float*)d_in[1];
    const float* V = (const float*)d_in[2];
    const void*  M = d_in[3];

    float* ctx  = (float*)d_out;                       // [B,S,D]
    float* attn = ctx + (size_t)Bb * Ss * Dd;          // [B,S,S]

    detect_mask<<<1, 256>>>((const unsigned*)M);
    attn_k1<0><<<Bb * (Ss / ROWS), 256>>>(Q, K, V, M, ctx, attn);
    attn_k1<1><<<Bb * (Ss / ROWS), 256>>>(Q, K, V, M, ctx, attn);
    attn_k1<2><<<Bb * (Ss / ROWS), 256>>>(Q, K, V, M, ctx, attn);
    attn_k2<<<Bb * Ss, 256>>>(attn);
}